// round 5
// baseline (speedup 1.0000x reference)
#include <cuda_runtime.h>
#include <math.h>

#define G        8
#define THREADS  256
#define MAXLEN_  100
#define MAXB     65536

// dynamic smem layout:
//   float4 Ws[32][256]   131072 B   (combined [k4][gate] weights, k<16:W_ih, k>=16:W_hh)
//   float4 Vs[G][32]       4096 B   (per-seg vec: [0..15]=x_t quads, [16..31]=h quads)
//   float  gates[G][256]   8192 B
#define SMEM_BYTES (131072 + 4096 + 8192)

__device__ int d_start[MAXB];
__device__ int d_end[MAXB];
__device__ int d_len[MAXB];
__device__ int d_order[MAXB];
__device__ int d_hist[MAXLEN_ + 2];
__device__ int d_offs[MAXLEN_ + 2];
__device__ int d_cursor[MAXLEN_ + 2];
__device__ int d_is64;

__global__ void k_init(int B) {
    int i = blockIdx.x * blockDim.x + threadIdx.x;
    if (i < B) { d_start[i] = 0; d_end[i] = 0; }
    if (i <= MAXLEN_) { d_hist[i] = 0; d_cursor[i] = 0; }
}

// Detect index dtype without ever reading past 4N bytes.
// int32 view word[N-1]: if index is int64 (values < 2^31) this is a high word
// (or a low word of a mid-sequence element only when N is odd, still compared
// against 0 -> mid element value > 0 gives int32 verdict, which is then the
// low-word-safe interpretation anyway for N odd only in pathological cases;
// for this problem N=500000 even -> deterministic). If index is int32 this is
// the largest sorted index (nonzero unless ALL indices are 0).
__global__ void k_detect(const int* __restrict__ w32, int N) {
    if (threadIdx.x == 0 && blockIdx.x == 0) {
        d_is64 = (w32[N - 1] == 0) ? 1 : 0;
    }
}

__global__ void k_bounds(const void* __restrict__ indexv, int N, int B) {
    int i = blockIdx.x * blockDim.x + threadIdx.x;
    if (i >= N) return;
    const int is64 = d_is64;
    int b, bp = -1, bn = -1;
    if (is64) {
        const long long* idx = (const long long*)indexv;
        b = (int)idx[i];
        if (i > 0) bp = (int)idx[i - 1];
        if (i < N - 1) bn = (int)idx[i + 1];
    } else {
        const int* idx = (const int*)indexv;
        b = idx[i];
        if (i > 0) bp = idx[i - 1];
        if (i < N - 1) bn = idx[i + 1];
    }
    if (b < 0 || b >= B) return;   // defensive: never scatter out of bounds
    if (i == 0 || bp != b) d_start[b] = i;
    if (i == N - 1 || bn != b) d_end[b] = i + 1;
}

__global__ void k_len(int B) {
    int b = blockIdx.x * blockDim.x + threadIdx.x;
    if (b >= B) return;
    int l = d_end[b] - d_start[b];
    if (l > MAXLEN_) l = MAXLEN_;
    if (l < 0) l = 0;
    d_len[b] = l;
    atomicAdd(&d_hist[l], 1);
}

// descending-length exclusive prefix: longest segments get lowest order slots
__global__ void k_scan() {
    if (threadIdx.x == 0) {
        int acc = 0;
        for (int l = MAXLEN_; l >= 0; --l) { d_offs[l] = acc; acc += d_hist[l]; }
    }
}

__global__ void k_scatter(int B) {
    int b = blockIdx.x * blockDim.x + threadIdx.x;
    if (b >= B) return;
    int l = d_len[b];
    int p = d_offs[l] + atomicAdd(&d_cursor[l], 1);
    if (p >= 0 && p < B) d_order[p] = b;
}

__device__ __forceinline__ float sigm_f(float v) {
    return 1.0f / (1.0f + __expf(-v));
}
__device__ __forceinline__ float tanh_f(float v) {
    // exact-ish tanh via fast exp; saturates correctly for |v| large
    return 1.0f - 2.0f / (__expf(2.0f * v) + 1.0f);
}

extern __shared__ float4 smem4[];

__global__ __launch_bounds__(THREADS, 1)
void k_lstm(const float* __restrict__ x,
            const float* __restrict__ W_ih,
            const float* __restrict__ W_hh,
            const float* __restrict__ b_ih,
            const float* __restrict__ b_hh,
            float* __restrict__ out,
            int B, int N) {
    float4* Ws = smem4;                       // [32][256] float4
    float4* Vs = smem4 + 32 * 256;            // [G][32] float4
    float*  Vf = (float*)Vs;                  // [G][128] floats (x:0..63, h:64..127)
    float*  gates = (float*)(Vs + G * 32);    // [G][256]
    __shared__ int s_start[G], s_len[G], s_segid[G], s_nsteps;

    const int t = threadIdx.x;

    // ---- stage weights: Ws[k4*256 + row] = row-quad k4 of combined [x;h] weight ----
    const float4* wih4 = (const float4*)W_ih;   // [256][16]
    const float4* whh4 = (const float4*)W_hh;   // [256][16]
    for (int idx = t; idx < 32 * 256; idx += THREADS) {
        int k4 = idx >> 8, row = idx & 255;
        Ws[idx] = (k4 < 16) ? wih4[row * 16 + k4] : whh4[row * 16 + (k4 - 16)];
    }

    if (t < G) {
        int gi  = blockIdx.x * G + t;
        int seg = (gi < B) ? d_order[gi] : -1;
        int st  = (seg >= 0) ? d_start[seg] : 0;
        int ln  = (seg >= 0) ? d_len[seg] : 0;
        // defensive clamps: never let a bad segment descriptor index x OOB
        if (st < 0) st = 0;
        if (st > N) st = N;
        if (ln > N - st) ln = N - st;
        if (ln < 0) ln = 0;
        s_segid[t] = seg;
        s_start[t] = st;
        s_len[t]   = ln;
    }
    if (t < G * 32) Vs[t] = make_float4(0.f, 0.f, 0.f, 0.f);

    const float bias = b_ih[t] + b_hh[t];
    float c0 = 0.f, c1 = 0.f;
    __syncthreads();

    if (t == 0) {
        int m = 0;
        #pragma unroll
        for (int g = 0; g < G; ++g) m = max(m, s_len[g]);
        s_nsteps = m;
    }
    // stage x for step 0
    const int pg = t >> 4, pq = t & 15;
    if (t < 128) {
        if (s_len[pg] > 0)
            Vs[pg * 32 + pq] = ((const float4*)x)[(size_t)s_start[pg] * 16 + pq];
    }
    __syncthreads();

    const int nsteps = s_nsteps;
    const int unit = t & 63;
    const int sb = (t >> 6) << 1;   // this thread updates segments sb and sb+1

    for (int step = 0; step < nsteps; ++step) {
        // prefetch x for step+1 (hidden under the GEMV)
        float4 nx = make_float4(0.f, 0.f, 0.f, 0.f);
        if (t < 128) {
            int ns = step + 1;
            if (ns < s_len[pg])
                nx = ((const float4*)x)[(size_t)(s_start[pg] + ns) * 16 + pq];
        }

        // ---- gate GEMV: gate t for G segments over combined [x;h] (K=128) ----
        float acc[G];
        #pragma unroll
        for (int g = 0; g < G; ++g) acc[g] = bias;
        #pragma unroll 4
        for (int k4 = 0; k4 < 32; ++k4) {
            float4 w = Ws[k4 * 256 + t];
            #pragma unroll
            for (int g = 0; g < G; ++g) {
                float4 v = Vs[g * 32 + k4];   // uniform across warp -> broadcast
                acc[g] = fmaf(w.x, v.x, acc[g]);
                acc[g] = fmaf(w.y, v.y, acc[g]);
                acc[g] = fmaf(w.z, v.z, acc[g]);
                acc[g] = fmaf(w.w, v.w, acc[g]);
            }
        }
        #pragma unroll
        for (int g = 0; g < G; ++g) gates[g * 256 + t] = acc[g];
        __syncthreads();

        // stage next x (x region of Vs only; h region untouched)
        if (t < 128) Vs[pg * 32 + pq] = nx;

        // ---- elementwise LSTM cell update; freeze finished segments ----
        {
            int sg = sb;
            if (step < s_len[sg]) {
                float gi = gates[sg * 256 + unit];
                float gf = gates[sg * 256 + 64 + unit];
                float gg = gates[sg * 256 + 128 + unit];
                float go = gates[sg * 256 + 192 + unit];
                float cn = sigm_f(gf) * c0 + sigm_f(gi) * tanh_f(gg);
                float hn = sigm_f(go) * tanh_f(cn);
                c0 = cn;
                Vf[sg * 128 + 64 + unit] = hn;
            }
            sg = sb + 1;
            if (step < s_len[sg]) {
                float gi = gates[sg * 256 + unit];
                float gf = gates[sg * 256 + 64 + unit];
                float gg = gates[sg * 256 + 128 + unit];
                float go = gates[sg * 256 + 192 + unit];
                float cn = sigm_f(gf) * c1 + sigm_f(gi) * tanh_f(gg);
                float hn = sigm_f(go) * tanh_f(cn);
                c1 = cn;
                Vf[sg * 128 + 64 + unit] = hn;
            }
        }
        __syncthreads();
    }

    // ---- emit last hidden state (zero-length segments emit the initial 0) ----
    {
        int sg = sb;
        if (s_segid[sg] >= 0)
            out[(size_t)s_segid[sg] * 64 + unit] = Vf[sg * 128 + 64 + unit];
        sg = sb + 1;
        if (s_segid[sg] >= 0)
            out[(size_t)s_segid[sg] * 64 + unit] = Vf[sg * 128 + 64 + unit];
    }
}

extern "C" void kernel_launch(void* const* d_in, const int* in_sizes, int n_in,
                              void* d_out, int out_size) {
    const float* x    = (const float*)d_in[0];
    const float* W_ih = (const float*)d_in[1];
    const float* W_hh = (const float*)d_in[2];
    const float* b_ih = (const float*)d_in[3];
    const float* b_hh = (const float*)d_in[4];
    const void*  indexv = d_in[5];
    float* out = (float*)d_out;

    int N = in_sizes[0] / 64;
    int B = out_size / 64;
    if (B > MAXB) B = MAXB;

    cudaFuncSetAttribute(k_lstm, cudaFuncAttributeMaxDynamicSharedMemorySize, SMEM_BYTES);

    int initN = (B > (MAXLEN_ + 1)) ? B : (MAXLEN_ + 1);
    k_init<<<(initN + 255) / 256, 256>>>(B);
    k_detect<<<1, 32>>>((const int*)indexv, N);
    k_bounds<<<(N + 255) / 256, 256>>>(indexv, N, B);
    k_len<<<(B + 255) / 256, 256>>>(B);
    k_scan<<<1, 32>>>();
    k_scatter<<<(B + 255) / 256, 256>>>(B);

    int nblk = (B + G - 1) / G;
    k_lstm<<<nblk, THREADS, SMEM_BYTES>>>(x, W_ih, W_hh, b_ih, b_hh, out, B, N);
}

// round 6
// speedup vs baseline: 1.0613x; 1.0613x over previous
#include <cuda_runtime.h>
#include <math.h>

#define MAXLEN_  100
#define MAXB     65536
#define MAXROWS  501760            // >= N=500000, row capacity of xg scratch

// ---------------- scratch: xg[n][gate-pair p] as packed f32x2 (u64) ----------------
__device__ unsigned long long d_xg[(size_t)MAXROWS * 128];   // 514 MB

__device__ int d_start[MAXB];
__device__ int d_end[MAXB];
__device__ int d_len[MAXB];
__device__ int d_order[MAXB];
__device__ int d_hist[MAXLEN_ + 2];
__device__ int d_offs[MAXLEN_ + 2];
__device__ int d_cursor[MAXLEN_ + 2];
__device__ int d_is64;

// ---------------- packed dual-fp32 FMA (Blackwell FFMA2) ----------------
__device__ __forceinline__ unsigned long long ffma2(unsigned long long a,
                                                    unsigned long long b,
                                                    unsigned long long c) {
    unsigned long long d;
    asm("fma.rn.f32x2 %0, %1, %2, %3;" : "=l"(d) : "l"(a), "l"(b), "l"(c));
    return d;
}
__device__ __forceinline__ unsigned long long pack2(float lo, float hi) {
    unsigned long long d;
    asm("mov.b64 %0, {%1, %2};" : "=l"(d) : "f"(lo), "f"(hi));
    return d;
}

// ---------------- prep ----------------
__global__ void k_init(int B) {
    int i = blockIdx.x * blockDim.x + threadIdx.x;
    if (i < B) { d_start[i] = 0; d_end[i] = 0; }
    if (i <= MAXLEN_) { d_hist[i] = 0; d_cursor[i] = 0; }
}

// int64-vs-int32 index dtype probe (never reads past 4N bytes)
__global__ void k_detect(const int* __restrict__ w32, int N) {
    if (threadIdx.x == 0 && blockIdx.x == 0) d_is64 = (w32[N - 1] == 0) ? 1 : 0;
}

__global__ void k_bounds(const void* __restrict__ indexv, int N, int B) {
    int i = blockIdx.x * blockDim.x + threadIdx.x;
    if (i >= N) return;
    const int is64 = d_is64;
    int b, bp = -1, bn = -1;
    if (is64) {
        const long long* idx = (const long long*)indexv;
        b = (int)idx[i];
        if (i > 0) bp = (int)idx[i - 1];
        if (i < N - 1) bn = (int)idx[i + 1];
    } else {
        const int* idx = (const int*)indexv;
        b = idx[i];
        if (i > 0) bp = idx[i - 1];
        if (i < N - 1) bn = idx[i + 1];
    }
    if (b < 0 || b >= B) return;
    if (i == 0 || bp != b) d_start[b] = i;
    if (i == N - 1 || bn != b) d_end[b] = i + 1;
}

__global__ void k_len(int B) {
    int b = blockIdx.x * blockDim.x + threadIdx.x;
    if (b >= B) return;
    int l = d_end[b] - d_start[b];
    if (l > MAXLEN_) l = MAXLEN_;
    if (l < 0) l = 0;
    d_len[b] = l;
    atomicAdd(&d_hist[l], 1);
}

__global__ void k_scan() {
    if (threadIdx.x == 0) {
        int acc = 0;
        for (int l = MAXLEN_; l >= 0; --l) { d_offs[l] = acc; acc += d_hist[l]; }
    }
}

__global__ void k_scatter(int B) {
    int b = blockIdx.x * blockDim.x + threadIdx.x;
    if (b >= B) return;
    int l = d_len[b];
    int p = d_offs[l] + atomicAdd(&d_cursor[l], 1);
    if (p >= 0 && p < B) d_order[p] = b;
}

__device__ __forceinline__ float sigm_f(float v) { return 1.0f / (1.0f + __expf(-v)); }
__device__ __forceinline__ float tanh_f(float v) { return 1.0f - 2.0f / (__expf(2.0f * v) + 1.0f); }

// =======================================================================
// k_xgemm: xg[n][g] = sum_f x[n][f] * W_ih[g][f] + (b_ih[g]+b_hh[g])
// gate-pair layout: xg stored as u64 (g=2p, 2p+1). Persistent grid-stride,
// 64-row tiles, FFMA2 inner loop.
//  smem: sW pairs 64KB  [k2*128+p] = (wA_k0,wB_k0,wA_k1,wB_k1)
//        sX dup   32KB  [r*32+k2]  = (x_k0,x_k0,x_k1,x_k1)
// =======================================================================
#define XG_SMEM (65536 + 32768)

extern __shared__ unsigned char smem_raw[];

__global__ __launch_bounds__(256, 2)
void k_xgemm(const float* __restrict__ x,
             const float* __restrict__ W_ih,
             const float* __restrict__ b_ih,
             const float* __restrict__ b_hh,
             int N) {
    float4* sW = (float4*)smem_raw;                 // 4096 entries
    float4* sX = (float4*)(smem_raw + 65536);       // 2048 entries
    const ulonglong2* sWu = (const ulonglong2*)sW;
    const ulonglong2* sXu = (const ulonglong2*)sX;

    const int t = threadIdx.x;
    const int p = t & 127;      // gate pair
    const int half = t >> 7;    // row half: 0 -> rows 0..31, 1 -> rows 32..63

    // stage weight pairs
    for (int idx = t; idx < 4096; idx += 256) {
        int k2 = idx >> 7, pp = idx & 127;
        sW[idx] = make_float4(W_ih[(2 * pp)     * 64 + 2 * k2],
                              W_ih[(2 * pp + 1) * 64 + 2 * k2],
                              W_ih[(2 * pp)     * 64 + 2 * k2 + 1],
                              W_ih[(2 * pp + 1) * 64 + 2 * k2 + 1]);
    }
    const unsigned long long bias2 =
        pack2(b_ih[2 * p] + b_hh[2 * p], b_ih[2 * p + 1] + b_hh[2 * p + 1]);

    const int ntiles = (N + 63) >> 6;
    for (int tile = blockIdx.x; tile < ntiles; tile += gridDim.x) {
        const int row0 = tile << 6;
        __syncthreads();   // protect previous iteration's sX reads
        // stage x tile, duplicated for f32x2
        #pragma unroll
        for (int i = 0; i < 8; ++i) {
            int idx = t + i * 256;            // 0..2047
            int r = idx >> 5, k2 = idx & 31;
            int row = row0 + r;
            float2 v = make_float2(0.f, 0.f);
            if (row < N) v = ((const float2*)x)[(size_t)row * 32 + k2];
            sX[r * 32 + k2] = make_float4(v.x, v.x, v.y, v.y);
        }
        __syncthreads();

        unsigned long long acc[32];
        #pragma unroll
        for (int r = 0; r < 32; ++r) acc[r] = bias2;

        const int rbase = half * 32;
        for (int k2 = 0; k2 < 32; ++k2) {
            ulonglong2 w = sWu[k2 * 128 + p];
            #pragma unroll
            for (int r = 0; r < 32; ++r) {
                ulonglong2 v = sXu[(rbase + r) * 32 + k2];   // warp-uniform -> broadcast
                acc[r] = ffma2(w.x, v.x, acc[r]);
                acc[r] = ffma2(w.y, v.y, acc[r]);
            }
        }

        #pragma unroll
        for (int r = 0; r < 32; ++r) {
            int row = row0 + rbase + r;
            if (row < N) d_xg[(size_t)row * 128 + p] = acc[r];
        }
    }
}

// =======================================================================
// k_lstm: recurrence only (K=64: h @ W_hh^T), gates seeded from d_xg.
// 128 threads (thread = gate pair p), G=8 segments per block, 2 blocks/SM.
//  smem: sW pairs 64KB, sV dup-h 4KB [seg][k2]=(h2k,h2k,h2k+1,h2k+1),
//        sG gates 8KB (u64 pairs == natural float[256] gate layout)
// =======================================================================
#define G        8
#define LT       128
#define L_SMEM   (65536 + 4096 + 8192)

__global__ __launch_bounds__(LT, 2)
void k_lstm(const float* __restrict__ W_hh,
            float* __restrict__ out,
            int B, int N) {
    float4* sW = (float4*)smem_raw;                       // 64KB
    float4* sV = (float4*)(smem_raw + 65536);             // 256 float4
    unsigned long long* sG = (unsigned long long*)(smem_raw + 65536 + 4096); // 1024 u64
    float2* sV2 = (float2*)sV;                            // sV2[seg*64 + unit] = (h,h)
    const ulonglong2* sWu = (const ulonglong2*)sW;
    const ulonglong2* sVu = (const ulonglong2*)sV;
    const float* gatesf = (const float*)sG;               // [seg][256]
    __shared__ int s_start[G], s_len[G], s_segid[G];

    const int t = threadIdx.x;    // == gate pair p

    // stage W_hh pairs
    for (int idx = t; idx < 4096; idx += LT) {
        int k2 = idx >> 7, pp = idx & 127;
        sW[idx] = make_float4(W_hh[(2 * pp)     * 64 + 2 * k2],
                              W_hh[(2 * pp + 1) * 64 + 2 * k2],
                              W_hh[(2 * pp)     * 64 + 2 * k2 + 1],
                              W_hh[(2 * pp + 1) * 64 + 2 * k2 + 1]);
    }
    // segment metadata
    if (t < G) {
        int gi  = blockIdx.x * G + t;
        int seg = (gi < B) ? d_order[gi] : -1;
        int st  = (seg >= 0) ? d_start[seg] : 0;
        int ln  = (seg >= 0) ? d_len[seg] : 0;
        if (st < 0) st = 0;
        if (st > N) st = N;
        if (ln > N - st) ln = N - st;
        if (ln < 0) ln = 0;
        s_segid[t] = seg;
        s_start[t] = st;
        s_len[t]   = ln;
    }
    // zero h
    #pragma unroll
    for (int i = t; i < 256; i += LT) sV[i] = make_float4(0.f, 0.f, 0.f, 0.f);
    __syncthreads();

    int nsteps = 0;
    #pragma unroll
    for (int s = 0; s < G; ++s) nsteps = max(nsteps, s_len[s]);

    // per-thread cell-state slots: lin = p + 128*j -> (seg, unit)
    float hreg[4], creg[4];
    int segj[4], unitj[4];
    #pragma unroll
    for (int j = 0; j < 4; ++j) {
        int lin = t + 128 * j;
        segj[j]  = lin >> 6;
        unitj[j] = lin & 63;
        hreg[j] = 0.f;
        creg[j] = 0.f;
    }

    // xg for step 0
    unsigned long long cur[G];
    #pragma unroll
    for (int s = 0; s < G; ++s)
        cur[s] = (0 < s_len[s]) ? d_xg[(size_t)s_start[s] * 128 + t] : 0ull;

    for (int step = 0; step < nsteps; ++step) {
        // prefetch xg for step+1 (hidden under FMA phase)
        unsigned long long nxt[G];
        #pragma unroll
        for (int s = 0; s < G; ++s) {
            int ns = step + 1;
            nxt[s] = (ns < s_len[s]) ? d_xg[(size_t)(s_start[s] + ns) * 128 + t] : 0ull;
        }

        // ---- gate pair GEMV over h (K=64) for G segments ----
        unsigned long long acc[G];
        #pragma unroll
        for (int s = 0; s < G; ++s) acc[s] = cur[s];
        #pragma unroll 4
        for (int k2 = 0; k2 < 32; ++k2) {
            ulonglong2 w = sWu[k2 * 128 + t];
            #pragma unroll
            for (int s = 0; s < G; ++s) {
                ulonglong2 v = sVu[s * 32 + k2];   // warp-uniform -> broadcast
                acc[s] = ffma2(w.x, v.x, acc[s]);
                acc[s] = ffma2(w.y, v.y, acc[s]);
            }
        }
        #pragma unroll
        for (int s = 0; s < G; ++s) sG[s * 128 + t] = acc[s];
        __syncthreads();

        // ---- cell update (freeze finished segments) ----
        #pragma unroll
        for (int j = 0; j < 4; ++j) {
            int seg = segj[j], unit = unitj[j];
            if (step < s_len[seg]) {
                float gi = gatesf[seg * 256 + unit];
                float gf = gatesf[seg * 256 + 64 + unit];
                float gg = gatesf[seg * 256 + 128 + unit];
                float go = gatesf[seg * 256 + 192 + unit];
                float cn = sigm_f(gf) * creg[j] + sigm_f(gi) * tanh_f(gg);
                float hn = sigm_f(go) * tanh_f(cn);
                creg[j] = cn;
                hreg[j] = hn;
                sV2[seg * 64 + unit] = make_float2(hn, hn);  // duplicated for f32x2
            }
        }
        __syncthreads();

        #pragma unroll
        for (int s = 0; s < G; ++s) cur[s] = nxt[s];
    }

    // ---- emit last hidden (zero-length segments emit 0) ----
    #pragma unroll
    for (int j = 0; j < 4; ++j) {
        int seg = segj[j];
        if (s_segid[seg] >= 0)
            out[(size_t)s_segid[seg] * 64 + unitj[j]] = hreg[j];
    }
}

extern "C" void kernel_launch(void* const* d_in, const int* in_sizes, int n_in,
                              void* d_out, int out_size) {
    const float* x    = (const float*)d_in[0];
    const float* W_ih = (const float*)d_in[1];
    const float* W_hh = (const float*)d_in[2];
    const float* b_ih = (const float*)d_in[3];
    const float* b_hh = (const float*)d_in[4];
    const void*  indexv = d_in[5];
    float* out = (float*)d_out;

    int N = in_sizes[0] / 64;
    int B = out_size / 64;
    if (B > MAXB) B = MAXB;
    if (N > MAXROWS) N = MAXROWS;

    cudaFuncSetAttribute(k_xgemm, cudaFuncAttributeMaxDynamicSharedMemorySize, XG_SMEM);
    cudaFuncSetAttribute(k_lstm,  cudaFuncAttributeMaxDynamicSharedMemorySize, L_SMEM);

    // xg pre-GEMM (independent of segment prep; same stream keeps ordering)
    k_xgemm<<<296, 256, XG_SMEM>>>(x, W_ih, b_ih, b_hh, N);

    int initN = (B > (MAXLEN_ + 1)) ? B : (MAXLEN_ + 1);
    k_init<<<(initN + 255) / 256, 256>>>(B);
    k_detect<<<1, 32>>>((const int*)indexv, N);
    k_bounds<<<(N + 255) / 256, 256>>>(indexv, N, B);
    k_len<<<(B + 255) / 256, 256>>>(B);
    k_scan<<<1, 32>>>();
    k_scatter<<<(B + 255) / 256, 256>>>(B);

    int nblk = (B + G - 1) / G;
    k_lstm<<<nblk, LT, L_SMEM>>>(W_hh, out, B, N);
}